// round 13
// baseline (speedup 1.0000x reference)
#include <cuda_runtime.h>
#include <cuda_bf16.h>
#include <math.h>
#include <stdint.h>

// Problem constants
#define ADIM 8
#define BDIM 16
#define HDIM 64
#define WDIM 64
#define SPATIAL (ADIM*BDIM*HDIM*WDIM)   // 524288
#define COUT 32
#define EPSV 1e-5f
#define NEG_SLOPE 0.2f

// smem plane: 34 rows (input h = h0-1 .. h0+32), stride 72 floats.
// input col ww maps to smem col ww+4 (interior 4..67); cols 0..3 / 68..71 zero.
#define PLSTRIDE 72
#define PLROWS   34
#define PLSZ     (PLROWS * PLSTRIDE)    // 2448 floats

typedef unsigned long long ull;

// Scratch (static device globals; runtime allocation is forbidden)
__device__ float g_buf1[COUT * SPATIAL];
__device__ float g_buf2[COUT * SPATIAL];
__device__ float2 g_stats1[COUT];
__device__ float2 g_stats2[COUT];

// ---------------------------------------------------------------------------
#define FMA2(d, a, b) \
    asm volatile("fma.rn.f32x2 %0, %1, %2, %0;" : "+l"(d) : "l"(a), "l"(b))

// u = (hi(a), lo(b))  -- unaligned middle pair
#define MIDPAIR(u, a, b) \
    asm volatile("{\n\t.reg .b32 l1, h1, l2, h2;\n\t" \
                 "mov.b64 {l1,h1}, %1;\n\t" \
                 "mov.b64 {l2,h2}, %2;\n\t" \
                 "mov.b64 %0, {h1, l2};\n\t}" \
                 : "=l"(u) : "l"(a), "l"(b))

#define CP_COMMIT() asm volatile("cp.async.commit_group;")
#define CP_WAIT0()  asm volatile("cp.async.wait_group 0;")

// Loader: 34 rows x 16 chunks of 16B = 544 cp.async, shift-only indexing.
// OOB rows (hh<0 or hh>=64) zero-filled via src-size 0.
__device__ __forceinline__ void load_plane(float* s, const float* xp,
                                           int h0, int tid)
{
    #pragma unroll
    for (int k = 0; k < 3; ++k) {
        const int e = tid + (k << 8);
        if (e < PLROWS * 16) {
            const int r = e >> 4;           // smem row 0..33
            const int c = e & 15;           // 16B chunk
            const int hh = h0 - 1 + r;
            const bool ok = (unsigned)hh < (unsigned)HDIM;
            uint32_t sa = (uint32_t)__cvta_generic_to_shared(
                              s + r * PLSTRIDE + 4 + (c << 2));
            const float* g = xp + (size_t)(ok ? hh : 0) * WDIM + (c << 2);
            asm volatile("cp.async.cg.shared.global [%0], [%1], 16, %2;"
                         :: "r"(sa), "l"(g), "r"(ok ? 16 : 0));
        }
    }
}

// ---------------------------------------------------------------------------
// Direct 4D conv, 3x3x3x3, pad 1, FFMA2 math.
// Block: 256 thr, tile 32H x 64W at fixed (a,b), 4 couts (grid = 128,2,8).
// Thread: 2H x 4W x 4co -> acc[4][2][2] packed pairs (32 regs).
// __launch_bounds__(256,3): 3 CTAs/SM -> 24 warps to hide LDS latency.
// ---------------------------------------------------------------------------
template<int CIN>
__global__ __launch_bounds__(256, 3)
void conv4d_kernel(const float* __restrict__ x,   // [CIN][A][B][H][W]
                   const float* __restrict__ w,   // [COUT][CIN][3][3][3][3]
                   float* __restrict__ y)         // [COUT][A][B][H][W]
{
    extern __shared__ float sm[];
    // [0 .. 2*PLSZ)        : two input plane buffers
    // [2*PLSZ .. )         : weights, dup-pairs: idx = ci*36 + kh*12 + kw*4 + co
    float2* wsm = reinterpret_cast<float2*>(sm + 2 * PLSZ);

    const int a   = blockIdx.x >> 4;
    const int b   = blockIdx.x & 15;
    const int h0  = blockIdx.y * 32;
    const int co0 = blockIdx.z * 4;

    const int tid   = threadIdx.x;
    const int tx    = tid & 15;          // 4 px in W: 4tx..4tx+3
    const int ty    = tid >> 4;          // 2 rows in H
    const int rbase = ty * 2;            // smem row of (out_h - 1) for ph0,kh0
    const int cb    = tx * 4 + 2;        // aligned pair window start (smem col)

    // One-time zero of border cols (0..3, 68..71) of both buffers.
    // 2 buf x 34 rows x 8 cols = 544 floats.
    #pragma unroll
    for (int k = 0; k < 3; ++k) {
        const int e = tid + (k << 8);
        if (e < 2 * PLROWS * 8) {
            const int bf = e >= PLROWS * 8;
            const int r  = (e - bf * PLROWS * 8) >> 3;
            const int c  = e & 7;
            sm[bf * PLSZ + r * PLSTRIDE + ((c < 4) ? c : (c + 64))] = 0.f;
        }
    }

    ull acc[4][2][2] = {};   // [co][ph][w-pair]

    int buf = 0;
    for (int da = 0; da < 3; ++da) {
        const int ia = a + da - 1;
        if ((unsigned)ia >= (unsigned)ADIM) continue;
        for (int db = 0; db < 3; ++db) {
            const int ib = b + db - 1;
            if ((unsigned)ib >= (unsigned)BDIM) continue;

            const float* xab = x + ((size_t)ia * BDIM + ib) * (HDIM * WDIM);

            __syncthreads();   // prior segment's compute done -> wsm reusable

            // Fill dup-pair weights for all (ci,kh,kw,co) of this (da,db)
            const int tap9 = (da * 3 + db) * 9;
            for (int t = tid; t < CIN * 36; t += 256) {
                const int co  = t & 3;
                const int q   = t >> 2;       // ci*9 + kh*3 + kw
                const int tap = q % 9;
                const int ci  = q / 9;
                const float v = w[((size_t)(co0 + co) * CIN + ci) * 81 + tap9 + tap];
                wsm[t] = make_float2(v, v);
            }

            load_plane(sm + buf * PLSZ, xab, h0, tid);
            CP_COMMIT();

            for (int ci = 0; ci < CIN; ++ci) {
                CP_WAIT0();        // own cp.async writes for plane ci landed
                __syncthreads();   // all writes visible; compute(ci-1) finished

                if (ci + 1 < CIN) {
                    load_plane(sm + (buf ^ 1) * PLSZ,
                               xab + (size_t)(ci + 1) * SPATIAL, h0, tid);
                    CP_COMMIT();
                }

                const float*  pl  = sm + buf * PLSZ;
                const float2* wci = wsm + ci * 36;

                // Row window registers, rolled across kh (fully unrolled).
                ull alA[4], odA[3], alB[4], odB[3];
                {
                    const float* rp = pl + rbase * PLSTRIDE + cb;
                    #pragma unroll
                    for (int m = 0; m < 4; ++m)
                        alA[m] = *reinterpret_cast<const ull*>(rp + 2 * m);
                    #pragma unroll
                    for (int m = 0; m < 3; ++m) MIDPAIR(odA[m], alA[m], alA[m + 1]);
                }

                #pragma unroll
                for (int kh = 0; kh < 3; ++kh) {
                    // B row = input row below A (ph1's kh-tap / next A)
                    const float* rp = pl + (rbase + kh + 1) * PLSTRIDE + cb;
                    #pragma unroll
                    for (int m = 0; m < 4; ++m)
                        alB[m] = *reinterpret_cast<const ull*>(rp + 2 * m);
                    #pragma unroll
                    for (int m = 0; m < 3; ++m) MIDPAIR(odB[m], alB[m], alB[m + 1]);

                    const float2* wk = wci + kh * 12;
                    #pragma unroll
                    for (int kw = 0; kw < 3; ++kw) {
                        #pragma unroll
                        for (int co = 0; co < 4; ++co) {
                            const ull ww = *reinterpret_cast<const ull*>(
                                               wk + kw * 4 + co);   // broadcast
                            #pragma unroll
                            for (int j = 0; j < 2; ++j) {
                                const ull xa = (kw == 0) ? odA[j]
                                             : (kw == 1) ? alA[j + 1] : odA[j + 1];
                                const ull xb = (kw == 0) ? odB[j]
                                             : (kw == 1) ? alB[j + 1] : odB[j + 1];
                                FMA2(acc[co][0][j], ww, xa);
                                FMA2(acc[co][1][j], ww, xb);
                            }
                        }
                    }
                    // roll: A <- B
                    #pragma unroll
                    for (int m = 0; m < 4; ++m) alA[m] = alB[m];
                    #pragma unroll
                    for (int m = 0; m < 3; ++m) odA[m] = odB[m];
                }
                buf ^= 1;
            }
        }
    }

    // Epilogue: one float4 per (co, ph)
    #pragma unroll
    for (int co = 0; co < 4; ++co) {
        float* yb = y + (((size_t)(co0 + co) * ADIM + a) * BDIM + b) * (HDIM * WDIM);
        #pragma unroll
        for (int ph = 0; ph < 2; ++ph) {
            const int h = h0 + rbase + ph;
            const float2 v0 = *reinterpret_cast<const float2*>(&acc[co][ph][0]);
            const float2 v1 = *reinterpret_cast<const float2*>(&acc[co][ph][1]);
            *reinterpret_cast<float4*>(yb + h * WDIM + tx * 4) =
                make_float4(v0.x, v0.y, v1.x, v1.y);
        }
    }
}

// ---------------------------------------------------------------------------
// Per-channel mean / rstd. One block per channel, deterministic.
// ---------------------------------------------------------------------------
__global__ __launch_bounds__(1024)
void stats_kernel(const float* __restrict__ buf, float2* __restrict__ stats)
{
    const int co = blockIdx.x;
    const float4* p = reinterpret_cast<const float4*>(buf + (size_t)co * SPATIAL);
    const int nvec = SPATIAL / 4;

    float s = 0.f, s2 = 0.f;
    for (int i = threadIdx.x; i < nvec; i += 1024) {
        float4 v = p[i];
        s  += v.x + v.y + v.z + v.w;
        s2 += v.x * v.x + v.y * v.y + v.z * v.z + v.w * v.w;
    }
    #pragma unroll
    for (int o = 16; o > 0; o >>= 1) {
        s  += __shfl_down_sync(0xffffffffu, s,  o);
        s2 += __shfl_down_sync(0xffffffffu, s2, o);
    }
    __shared__ float rs[32], rs2[32];
    const int lane = threadIdx.x & 31, wid = threadIdx.x >> 5;
    if (lane == 0) { rs[wid] = s; rs2[wid] = s2; }
    __syncthreads();
    if (wid == 0) {
        s  = rs[lane];
        s2 = rs2[lane];
        #pragma unroll
        for (int o = 16; o > 0; o >>= 1) {
            s  += __shfl_down_sync(0xffffffffu, s,  o);
            s2 += __shfl_down_sync(0xffffffffu, s2, o);
        }
        if (lane == 0) {
            const float inv_n = 1.0f / (float)SPATIAL;
            const float mean  = s * inv_n;
            const float var   = fmaxf(s2 * inv_n - mean * mean, 0.f);
            stats[co] = make_float2(mean, rsqrtf(var + EPSV));
        }
    }
}

// ---------------------------------------------------------------------------
// out = leaky_relu((in - mean) * rstd)
// ---------------------------------------------------------------------------
__global__ __launch_bounds__(256)
void normleaky_kernel(const float* __restrict__ in,
                      const float2* __restrict__ stats,
                      float* __restrict__ out)
{
    const int nvec = COUT * SPATIAL / 4;
    const float4* ip = reinterpret_cast<const float4*>(in);
    float4* op = reinterpret_cast<float4*>(out);
    for (int i = blockIdx.x * blockDim.x + threadIdx.x; i < nvec;
         i += gridDim.x * blockDim.x) {
        const int co = (i * 4) >> 19;
        const float2 st = stats[co];
        float4 v = ip[i];
        float a0 = (v.x - st.x) * st.y;
        float a1 = (v.y - st.x) * st.y;
        float a2 = (v.z - st.x) * st.y;
        float a3 = (v.w - st.x) * st.y;
        v.x = a0 >= 0.f ? a0 : NEG_SLOPE * a0;
        v.y = a1 >= 0.f ? a1 : NEG_SLOPE * a1;
        v.z = a2 >= 0.f ? a2 : NEG_SLOPE * a2;
        v.w = a3 >= 0.f ? a3 : NEG_SLOPE * a3;
        op[i] = v;
    }
}

// ---------------------------------------------------------------------------
extern "C" void kernel_launch(void* const* d_in, const int* in_sizes, int n_in,
                              void* d_out, int out_size)
{
    (void)in_sizes; (void)n_in; (void)out_size;
    const float* image = (const float*)d_in[0];
    const float* w1    = (const float*)d_in[1];
    const float* w2    = (const float*)d_in[2];
    float* out = (float*)d_out;

    float*  buf1; cudaGetSymbolAddress((void**)&buf1, g_buf1);
    float*  buf2; cudaGetSymbolAddress((void**)&buf2, g_buf2);
    float2* st1;  cudaGetSymbolAddress((void**)&st1,  g_stats1);
    float2* st2;  cudaGetSymbolAddress((void**)&st2,  g_stats2);

    const int smem16 = (2 * PLSZ + 16 * 36 * 2) * 4;   // 24192 B
    const int smem32 = (2 * PLSZ + 32 * 36 * 2) * 4;   // 28800 B
    cudaFuncSetAttribute(conv4d_kernel<16>,
                         cudaFuncAttributeMaxDynamicSharedMemorySize, smem16);
    cudaFuncSetAttribute(conv4d_kernel<32>,
                         cudaFuncAttributeMaxDynamicSharedMemorySize, smem32);

    const dim3 cgrid(ADIM * BDIM, HDIM / 32, COUT / 4);   // (128, 2, 8)

    conv4d_kernel<16><<<cgrid, 256, smem16>>>(image, w1, buf1);
    stats_kernel<<<COUT, 1024>>>(buf1, st1);
    normleaky_kernel<<<2048, 256>>>(buf1, st1, buf1);

    conv4d_kernel<32><<<cgrid, 256, smem32>>>(buf1, w2, buf2);
    stats_kernel<<<COUT, 1024>>>(buf2, st2);
    normleaky_kernel<<<2048, 256>>>(buf2, st2, out);
}

// round 15
// speedup vs baseline: 1.1975x; 1.1975x over previous
#include <cuda_runtime.h>
#include <cuda_bf16.h>
#include <math.h>
#include <stdint.h>

// ---------------------------------------------------------------- constants
#define ADIM 8
#define BDIM 16
#define HDIM 64
#define WDIM 64
#define SPATIAL (ADIM*BDIM*HDIM*WDIM)   // 524288
#define COUT 32
#define EPSV 1e-5f
#define NEG_SLOPE 0.2f

#define NPLANE 128            // ab = a*16+b
#define GW 66                 // padded slot grid width (h,w = -1..64)
#define SLOTS (GW*GW)         // 4356
#define MARG 72               // zero slots before payload
#define PSTRIDE 4752          // slots per (ab) plane (72 + 4608 + 67 <= 4752)
#define TGROUPS 18            // 18 * 256 = 4608 >= 4356
#define SLAB 392              // A slab rows per (block, dadb)

// ------------------------------------------------------------- scratch
__device__ float g_buf1[COUT * SPATIAL];
__device__ float g_buf2[COUT * SPATIAL];
__device__ float2 g_stats1[COUT];
__device__ float2 g_stats2[COUT];
__device__ __nv_bfloat16 g_X1[(size_t)NPLANE * PSTRIDE * 40];  // rows of 40 bf16
__device__ __nv_bfloat16 g_X2[(size_t)NPLANE * PSTRIDE * 72];  // rows of 72 bf16
// B fragments: [dadb(9)][tap(9)][chunk(NBC)][ntile(4)][lane(32)] x uint2
__device__ uint2 g_Bf1[9 * 9 * 2 * 4 * 32];
__device__ uint2 g_Bf2[9 * 9 * 4 * 4 * 32];

// product tables: (A kchunk, B chunk) pairs
__constant__ int PA16[3] = {0, 1, 0};
__constant__ int PB16[3] = {0, 0, 1};
__constant__ int PA32[6] = {0, 1, 2, 3, 0, 1};
__constant__ int PB32[6] = {0, 1, 0, 1, 2, 3};
__constant__ int ROWOFF[9] = {-GW-1, -GW, -GW+1, -1, 0, 1, GW-1, GW, GW+1};

// ------------------------------------------------------------- helpers
#define CP16(sa, g) \
    asm volatile("cp.async.cg.shared.global [%0], [%1], 16;" :: "r"(sa), "l"(g))
#define CP_COMMIT() asm volatile("cp.async.commit_group;")
#define CP_WAIT0()  asm volatile("cp.async.wait_group 0;" ::: "memory")

__device__ __forceinline__ uint32_t s2u(const void* p) {
    return (uint32_t)__cvta_generic_to_shared(p);
}
__device__ __forceinline__ unsigned short bfbits(__nv_bfloat16 v) {
    return *reinterpret_cast<unsigned short*>(&v);
}

#define LDMATX4(r, addr) \
    asm volatile("ldmatrix.sync.aligned.m8n8.x4.shared.b16 {%0,%1,%2,%3}, [%4];" \
        : "=r"((r)[0]), "=r"((r)[1]), "=r"((r)[2]), "=r"((r)[3]) : "r"(addr))

#define MMA16816(d, aq, b0, b1) \
    asm volatile("mma.sync.aligned.m16n8k16.row.col.f32.bf16.bf16.f32 " \
        "{%0,%1,%2,%3}, {%4,%5,%6,%7}, {%8,%9}, {%0,%1,%2,%3};" \
        : "+f"((d)[0]), "+f"((d)[1]), "+f"((d)[2]), "+f"((d)[3]) \
        : "r"((aq)[0]), "r"((aq)[1]), "r"((aq)[2]), "r"((aq)[3]), \
          "r"(b0), "r"(b1))

// ------------------------------------------------------------- weight prep
// One thread per (dadb, tap, chunk, ntile, lane) -> uint2 frag {b0, b1}.
// b0 = {B[k0][n], B[k0+1][n]}, b1 = {B[k0+8][n], B[k0+9][n]}, k0=(lane&3)*2,
// n = lane>>2, co = ntile*8 + n.  chunk meaning (conv2): 0:hi(ci=k) 1:hi(16+k)
// 2:lo(k) 3:lo(16+k).  conv1: 0:hi(k) 1:lo(k).
template<int CIN, int NBC>
__global__ void prep_w(const float* __restrict__ w, uint2* __restrict__ Bf)
{
    const int t = blockIdx.x * 256 + threadIdx.x;
    if (t >= 9 * 9 * NBC * 4 * 32) return;
    const int lane = t & 31;
    const int nt   = (t >> 5) & 3;
    int u = t >> 7;
    const int chunk = u % NBC;  u /= NBC;
    const int tap   = u % 9;
    const int dadb  = u / 9;

    const int n  = lane >> 2;
    const int k0 = (lane & 3) * 2;
    const int co = nt * 8 + n;
    const bool wantlo = (chunk >= NBC / 2);
    const int cibase  = (chunk % (NBC / 2)) * 16;

    unsigned short v[4];
    #pragma unroll
    for (int j = 0; j < 4; ++j) {
        const int k  = ((j >> 1) * 8) + k0 + (j & 1);   // k0,k0+1,k0+8,k0+9
        const int ci = cibase + k;
        const float wv = w[((size_t)co * CIN + ci) * 81 + dadb * 9 + tap];
        const __nv_bfloat16 hi = __float2bfloat16(wv);
        const __nv_bfloat16 lo = __float2bfloat16(wv - __bfloat162float(hi));
        v[j] = bfbits(wantlo ? lo : hi);
    }
    uint2 r;
    r.x = ((uint32_t)v[1] << 16) | v[0];
    r.y = ((uint32_t)v[3] << 16) | v[2];
    Bf[t] = r;
}

// ------------------------------------------------------------- X prep
// conv1 rows: 40 bf16 = [hi(16) | lo(16) | pad(8)]; one thread per 16B chunk.
__global__ void prep_x1(const float* __restrict__ img, __nv_bfloat16* __restrict__ X)
{
    const long gid = (long)blockIdx.x * 256 + threadIdx.x;
    if (gid >= (long)NPLANE * PSTRIDE * 5) return;
    const int c  = (int)(gid % 5);
    const int s  = (int)((gid / 5) % PSTRIDE);
    const int ab = (int)(gid / (5L * PSTRIDE));

    unsigned short row[8] = {0,0,0,0,0,0,0,0};
    const int slot = s - MARG;
    if (slot >= 0 && slot < SLOTS && c < 4) {
        const int ph = slot / GW, pw = slot % GW;
        if (ph >= 1 && ph <= 64 && pw >= 1 && pw <= 64) {
            const int base = ab * 4096 + (ph - 1) * 64 + (pw - 1);
            const bool wantlo = (c >= 2);
            const int ci0 = (c % 2) * 8;
            #pragma unroll
            for (int j = 0; j < 8; ++j) {
                const float v = img[(size_t)(ci0 + j) * SPATIAL + base];
                const __nv_bfloat16 hi = __float2bfloat16(v);
                row[j] = bfbits(wantlo
                    ? __float2bfloat16(v - __bfloat162float(hi)) : hi);
            }
        }
    }
    *reinterpret_cast<uint4*>(X + ((size_t)ab * PSTRIDE + s) * 40 + c * 8) =
        *reinterpret_cast<const uint4*>(row);
}

// conv2 rows: 72 bf16 = [hi(32) | lo(32) | pad(8)]; fused instnorm + leaky.
__global__ void prep_x2(const float* __restrict__ in, const float2* __restrict__ st,
                        __nv_bfloat16* __restrict__ X)
{
    const long gid = (long)blockIdx.x * 256 + threadIdx.x;
    if (gid >= (long)NPLANE * PSTRIDE * 9) return;
    const int c  = (int)(gid % 9);
    const int s  = (int)((gid / 9) % PSTRIDE);
    const int ab = (int)(gid / (9L * PSTRIDE));

    unsigned short row[8] = {0,0,0,0,0,0,0,0};
    const int slot = s - MARG;
    if (slot >= 0 && slot < SLOTS && c < 8) {
        const int ph = slot / GW, pw = slot % GW;
        if (ph >= 1 && ph <= 64 && pw >= 1 && pw <= 64) {
            const int base = ab * 4096 + (ph - 1) * 64 + (pw - 1);
            const bool wantlo = (c >= 4);
            const int ci0 = (c % 4) * 8;
            #pragma unroll
            for (int j = 0; j < 8; ++j) {
                const int ci = ci0 + j;
                const float2 s2 = st[ci];
                float v = in[(size_t)ci * SPATIAL + base];
                v = (v - s2.x) * s2.y;
                v = (v >= 0.f) ? v : NEG_SLOPE * v;
                const __nv_bfloat16 hi = __float2bfloat16(v);
                row[j] = bfbits(wantlo
                    ? __float2bfloat16(v - __bfloat162float(hi)) : hi);
            }
        }
    }
    *reinterpret_cast<uint4*>(X + ((size_t)ab * PSTRIDE + s) * 72 + c * 8) =
        *reinterpret_cast<const uint4*>(row);
}

// ------------------------------------------------------------- MMA conv
// Block: 256 thr = 8 warps; M = 256 slots (warp M32 = 2 x m16), N = 32.
// Accumulate over (da,db) x 9 taps; A slab reloaded per (da,db) via cp.async.
template<int CIN>
__global__ __launch_bounds__(256, 2)
void conv_mma(const __nv_bfloat16* __restrict__ X,
              const uint2* __restrict__ Bf,
              float* __restrict__ y)
{
    constexpr int ROWE  = (CIN == 16) ? 40 : 72;     // bf16 per A row
    constexpr int ROWB  = ROWE * 2;                  // bytes (80 | 144)
    constexpr int NKA   = CIN / 8;                   // A kchunks (2 | 4)
    constexpr int NBC   = CIN / 8;                   // B chunks  (2 | 4)
    constexpr int NPROD = (CIN == 16) ? 3 : 6;
    constexpr int ABYTES = SLAB * ROWB;
    constexpr int BBYTES = 9 * NBC * 4 * 256;

    extern __shared__ char smem[];
    const uint32_t Abase = s2u(smem);
    const uint32_t Bbase = Abase + ABYTES;

    const int ab = blockIdx.x, a = ab >> 4, b = ab & 15;
    const int tg = blockIdx.y;
    const int tid = threadIdx.x, warp = tid >> 5, lane = tid & 31;
    const int sidx0 = tg * 256 + 5;          // slab global row start (s index)

    float acc[2][4][4] = {};                 // [mtile][ntile][frag]

    for (int da = 0; da < 3; ++da) {
        const int ia = a + da - 1;
        if ((unsigned)ia >= (unsigned)ADIM) continue;
        for (int db = 0; db < 3; ++db) {
            const int ib = b + db - 1;
            if ((unsigned)ib >= (unsigned)BDIM) continue;
            const int iab = ia * 16 + ib;

            __syncthreads();   // previous tap-compute done; smem reusable

            const char* ag = (const char*)(X + ((size_t)iab * PSTRIDE + sidx0) * ROWE);
            for (int e = tid; e < ABYTES / 16; e += 256)
                CP16(Abase + e * 16, ag + (size_t)e * 16);
            const char* bg = (const char*)(Bf + (size_t)(da * 3 + db) * 9 * NBC * 4 * 32);
            for (int e = tid; e < BBYTES / 16; e += 256)
                CP16(Bbase + e * 16, bg + (size_t)e * 16);
            CP_COMMIT();
            CP_WAIT0();
            __syncthreads();

            #pragma unroll 1
            for (int tap = 0; tap < 9; ++tap) {
                // B fragments for this tap (per-lane layout, conflict-free)
                uint32_t bq[NBC][4][2];
                #pragma unroll
                for (int ch = 0; ch < NBC; ++ch)
                    #pragma unroll
                    for (int nt = 0; nt < 4; ++nt) {
                        const uint32_t addr = Bbase +
                            ((((tap * NBC + ch) * 4 + nt) * 32 + lane) << 3);
                        asm volatile("ld.shared.v2.b32 {%0,%1}, [%2];"
                            : "=r"(bq[ch][nt][0]), "=r"(bq[ch][nt][1]) : "r"(addr));
                    }

                const int rowoff = ROWOFF[tap];
                #pragma unroll
                for (int mt = 0; mt < 2; ++mt) {
                    const int baserow = 67 + rowoff + warp * 32 + mt * 16 + (lane & 15);
                    uint32_t aq[NKA][4];
                    #pragma unroll
                    for (int kc = 0; kc < NKA; ++kc) {
                        const uint32_t addr = Abase + baserow * ROWB +
                                              kc * 32 + ((lane >> 4) << 4);
                        LDMATX4(aq[kc], addr);
                    }
                    #pragma unroll
                    for (int nt = 0; nt < 4; ++nt)
                        #pragma unroll
                        for (int p = 0; p < NPROD; ++p) {
                            const int ka = (CIN == 16) ? PA16[p] : PA32[p];
                            const int kb = (CIN == 16) ? PB16[p] : PB32[p];
                            MMA16816(acc[mt][nt], aq[ka],
                                     bq[kb][nt][0], bq[kb][nt][1]);
                        }
                }
            }
        }
    }

    // Epilogue: scatter valid interior slots to y[co][spatial]
    const int slotb = tg * 256 + warp * 32;
    #pragma unroll
    for (int mt = 0; mt < 2; ++mt)
        #pragma unroll
        for (int half = 0; half < 2; ++half) {
            const int slot = slotb + mt * 16 + (lane >> 2) + half * 8;
            if (slot < SLOTS) {
                const int ph = slot / GW, pw = slot % GW;
                if (ph >= 1 && ph <= 64 && pw >= 1 && pw <= 64) {
                    float* yb = y + ab * 4096 + (ph - 1) * 64 + (pw - 1);
                    #pragma unroll
                    for (int nt = 0; nt < 4; ++nt)
                        #pragma unroll
                        for (int cp = 0; cp < 2; ++cp) {
                            const int co = nt * 8 + (lane & 3) * 2 + cp;
                            yb[(size_t)co * SPATIAL] = acc[mt][nt][half * 2 + cp];
                        }
                }
            }
        }
}

// ------------------------------------------------------------- stats / norm
__global__ __launch_bounds__(1024)
void stats_kernel(const float* __restrict__ buf, float2* __restrict__ stats)
{
    const int co = blockIdx.x;
    const float4* p = reinterpret_cast<const float4*>(buf + (size_t)co * SPATIAL);
    const int nvec = SPATIAL / 4;

    float s = 0.f, s2 = 0.f;
    for (int i = threadIdx.x; i < nvec; i += 1024) {
        float4 v = p[i];
        s  += v.x + v.y + v.z + v.w;
        s2 += v.x * v.x + v.y * v.y + v.z * v.z + v.w * v.w;
    }
    #pragma unroll
    for (int o = 16; o > 0; o >>= 1) {
        s  += __shfl_down_sync(0xffffffffu, s,  o);
        s2 += __shfl_down_sync(0xffffffffu, s2, o);
    }
    __shared__ float rs[32], rs2[32];
    const int lane = threadIdx.x & 31, wid = threadIdx.x >> 5;
    if (lane == 0) { rs[wid] = s; rs2[wid] = s2; }
    __syncthreads();
    if (wid == 0) {
        s  = rs[lane];
        s2 = rs2[lane];
        #pragma unroll
        for (int o = 16; o > 0; o >>= 1) {
            s  += __shfl_down_sync(0xffffffffu, s,  o);
            s2 += __shfl_down_sync(0xffffffffu, s2, o);
        }
        if (lane == 0) {
            const float inv_n = 1.0f / (float)SPATIAL;
            const float mean  = s * inv_n;
            const float var   = fmaxf(s2 * inv_n - mean * mean, 0.f);
            stats[co] = make_float2(mean, rsqrtf(var + EPSV));
        }
    }
}

__global__ __launch_bounds__(256)
void normleaky_kernel(const float* __restrict__ in,
                      const float2* __restrict__ stats,
                      float* __restrict__ out)
{
    const int nvec = COUT * SPATIAL / 4;
    const float4* ip = reinterpret_cast<const float4*>(in);
    float4* op = reinterpret_cast<float4*>(out);
    for (int i = blockIdx.x * blockDim.x + threadIdx.x; i < nvec;
         i += gridDim.x * blockDim.x) {
        const int co = (i * 4) >> 19;
        const float2 st = stats[co];
        float4 v = ip[i];
        float a0 = (v.x - st.x) * st.y;
        float a1 = (v.y - st.x) * st.y;
        float a2 = (v.z - st.x) * st.y;
        float a3 = (v.w - st.x) * st.y;
        v.x = a0 >= 0.f ? a0 : NEG_SLOPE * a0;
        v.y = a1 >= 0.f ? a1 : NEG_SLOPE * a1;
        v.z = a2 >= 0.f ? a2 : NEG_SLOPE * a2;
        v.w = a3 >= 0.f ? a3 : NEG_SLOPE * a3;
        op[i] = v;
    }
}

// ------------------------------------------------------------- launch
extern "C" void kernel_launch(void* const* d_in, const int* in_sizes, int n_in,
                              void* d_out, int out_size)
{
    (void)in_sizes; (void)n_in; (void)out_size;
    const float* image = (const float*)d_in[0];
    const float* w1    = (const float*)d_in[1];
    const float* w2    = (const float*)d_in[2];
    float* out = (float*)d_out;

    float*  buf1; cudaGetSymbolAddress((void**)&buf1, g_buf1);
    float*  buf2; cudaGetSymbolAddress((void**)&buf2, g_buf2);
    float2* st1;  cudaGetSymbolAddress((void**)&st1,  g_stats1);
    float2* st2;  cudaGetSymbolAddress((void**)&st2,  g_stats2);
    __nv_bfloat16* x1; cudaGetSymbolAddress((void**)&x1, g_X1);
    __nv_bfloat16* x2; cudaGetSymbolAddress((void**)&x2, g_X2);
    uint2* bf1; cudaGetSymbolAddress((void**)&bf1, g_Bf1);
    uint2* bf2; cudaGetSymbolAddress((void**)&bf2, g_Bf2);

    const int smem1 = SLAB * 80  + 9 * 2 * 4 * 256;   // 31360 + 18432 = 49792
    const int smem2 = SLAB * 144 + 9 * 4 * 4 * 256;   // 56448 + 36864 = 93312
    cudaFuncSetAttribute(conv_mma<16>,
                         cudaFuncAttributeMaxDynamicSharedMemorySize, smem1);
    cudaFuncSetAttribute(conv_mma<32>,
                         cudaFuncAttributeMaxDynamicSharedMemorySize, smem2);

    const dim3 mgrid(NPLANE, TGROUPS);
    const int px1 = (int)(((long)NPLANE * PSTRIDE * 5 + 255) / 256);
    const int px2 = (int)(((long)NPLANE * PSTRIDE * 9 + 255) / 256);

    prep_w<16, 2><<<81, 256>>>(w1, bf1);
    prep_w<32, 4><<<162, 256>>>(w2, bf2);
    prep_x1<<<px1, 256>>>(image, x1);

    conv_mma<16><<<mgrid, 256, smem1>>>(x1, bf1, buf1);
    stats_kernel<<<COUT, 1024>>>(buf1, st1);
    prep_x2<<<px2, 256>>>(buf1, st1, x2);

    conv_mma<32><<<mgrid, 256, smem2>>>(x2, bf2, buf2);
    stats_kernel<<<COUT, 1024>>>(buf2, st2);
    normleaky_kernel<<<2048, 256>>>(buf2, st2, out);
}